// round 11
// baseline (speedup 1.0000x reference)
#include <cuda_runtime.h>
#include <cuda_fp16.h>
#include <cstdint>

// ---------------------------------------------------------------------------
// QuantLinearTensorWise: y[8192,16384] = x[8192,4096] @ (W*scale)^T + bias
// Portable tensor-core path (compute_103 target): ldmatrix + mma.sync m16n8k16.
// R10: R9 (BK=128, STAGES=2, 32 barrier events) with the A-load slice count
//      FIXED (was loading only half the A tile -> NaN). Loads A@ks0, B@ks1-4,
//      commit@ks4 for more wait slack.
// ---------------------------------------------------------------------------

#define IN_F   4096
#define OUT_F  16384
#define NROWS  8192

#define BM 128
#define BN 256
#define BK 128
#define STAGES 2
#define THREADS 256
#define K_ITERS (IN_F / BK)        // 32
#define KS_STEPS (BK / 16)         // 8
#define TILES_M (NROWS / BM)       // 64
#define TILES_N (OUT_F / BN)       // 64
#define GROUP_M 8

// padded smem rows: 128 halves data + 8 halves pad = 136 halves = 272 bytes
#define SROW 136
#define TILE_A_BYTES (BM * SROW * 2)               // 34816
#define TILE_B_BYTES (BN * SROW * 2)               // 69632
#define STAGE_BYTES (TILE_A_BYTES + TILE_B_BYTES)  // 104448
#define SMEM_TOTAL (STAGES * STAGE_BYTES)          // 208896

// fp16 scratch
__device__ __half g_xh[(size_t)NROWS * IN_F];
__device__ __half g_wh[(size_t)OUT_F * IN_F];

// ---------------------------------------------------------------------------
// Conversion kernels
// ---------------------------------------------------------------------------
__global__ void k_convert_x(const float4* __restrict__ x, int n4) {
    int i = blockIdx.x * blockDim.x + threadIdx.x;
    if (i < n4) {
        float4 v = x[i];
        __half2* o = reinterpret_cast<__half2*>(g_xh);
        o[2 * i]     = __floats2half2_rn(v.x, v.y);
        o[2 * i + 1] = __floats2half2_rn(v.z, v.w);
    }
}

__global__ void k_convert_w(const int4* __restrict__ w, int n4) {
    int i = blockIdx.x * blockDim.x + threadIdx.x;
    if (i < n4) {
        int4 v = w[i];
        __half2* o = reinterpret_cast<__half2*>(g_wh);
        o[2 * i]     = __halves2half2(__int2half_rn(v.x), __int2half_rn(v.y));
        o[2 * i + 1] = __halves2half2(__int2half_rn(v.z), __int2half_rn(v.w));
    }
}

// ---------------------------------------------------------------------------
// PTX helpers (portable sm_80+)
// ---------------------------------------------------------------------------
__device__ __forceinline__ uint32_t smem_u32(const void* p) {
    uint32_t a;
    asm("{ .reg .u64 t; cvta.to.shared.u64 t, %1; cvt.u32.u64 %0, t; }"
        : "=r"(a) : "l"(p));
    return a;
}

__device__ __forceinline__ void cp_async16(uint32_t dst, const void* src) {
    asm volatile("cp.async.cg.shared.global [%0], [%1], 16;"
                 :: "r"(dst), "l"(src) : "memory");
}

__device__ __forceinline__ void cp_commit() {
    asm volatile("cp.async.commit_group;" ::: "memory");
}

__device__ __forceinline__ void cp_wait0() {
    asm volatile("cp.async.wait_group 0;" ::: "memory");
}

__device__ __forceinline__ void ldmx4(uint32_t* r, uint32_t addr) {
    asm volatile("ldmatrix.sync.aligned.m8n8.x4.shared.b16 {%0,%1,%2,%3}, [%4];"
                 : "=r"(r[0]), "=r"(r[1]), "=r"(r[2]), "=r"(r[3]) : "r"(addr));
}

__device__ __forceinline__ void mma16816(float* d, const uint32_t* a,
                                         const uint32_t* b) {
    asm volatile(
        "mma.sync.aligned.m16n8k16.row.col.f32.f16.f16.f32 "
        "{%0,%1,%2,%3}, {%4,%5,%6,%7}, {%8,%9}, {%0,%1,%2,%3};"
        : "+f"(d[0]), "+f"(d[1]), "+f"(d[2]), "+f"(d[3])
        : "r"(a[0]), "r"(a[1]), "r"(a[2]), "r"(a[3]), "r"(b[0]), "r"(b[1]));
}

// ---------------------------------------------------------------------------
// Stage load slices.
// A tile: 128 rows x 16 chunks = 2048 16B-chunks -> 1 slice of 8/thr.
// B tile: 256 rows x 16 chunks = 4096 16B-chunks -> 4 slices of 4/thr.
// Row pitch = SROW*2 = 272 B (16 data chunks + 1 pad chunk).
// ---------------------------------------------------------------------------
__device__ __forceinline__ void load_A_full(uint32_t stage_base, int kt,
                                            int m0, int tid) {
    int k0 = kt * BK;
#pragma unroll
    for (int h = 0; h < 8; h++) {
        int idx = tid + h * THREADS;
        int row = idx >> 4, c = idx & 15;
        uint32_t off = (uint32_t)(row * (SROW * 2) + c * 16);
        cp_async16(stage_base + off,
                   g_xh + (size_t)(m0 + row) * IN_F + k0 + c * 8);
    }
}

__device__ __forceinline__ void load_B_slice(uint32_t stage_base, int kt,
                                             int n0, int tid, int sl) {
    int k0 = kt * BK;
    uint32_t bB = stage_base + TILE_A_BYTES;
#pragma unroll
    for (int h = 0; h < 4; h++) {
        int idx = tid + (sl * 4 + h) * THREADS;
        int row = idx >> 4, c = idx & 15;
        uint32_t off = (uint32_t)(row * (SROW * 2) + c * 16);
        cp_async16(bB + off, g_wh + (size_t)(n0 + row) * IN_F + k0 + c * 8);
    }
}

// ---------------------------------------------------------------------------
// GEMM kernel: warp grid 2(M) x 4(N), warp tile 64x64, cross-tile frag pipe
// ---------------------------------------------------------------------------
__global__ void __launch_bounds__(THREADS, 1)
gemm_hmma_kernel(const float* __restrict__ scale_p,
                 const float* __restrict__ bias,
                 float* __restrict__ out) {
    extern __shared__ char smem[];
    uint32_t sb = smem_u32(smem);
    int tid = threadIdx.x;
    int lane = tid & 31;
    int warp = tid >> 5;     // 0..7
    int wm = warp & 1;       // M dir: 64 rows
    int wn = warp >> 1;      // N dir: 0..3, 64 cols

    // tile raster with GROUP_M swizzle
    int pid = blockIdx.x;
    int per_group = GROUP_M * TILES_N;
    int g = pid / per_group;
    int rem = pid - g * per_group;
    int mt = g * GROUP_M + (rem % GROUP_M);
    int nt = rem / GROUP_M;
    int m0 = mt * BM, n0 = nt * BN;

    // ldmatrix lane address components (halves)
    int ar = (lane & 7) + ((lane >> 3) & 1) * 8;
    int ac = (lane >> 4) * 8;
    int bn_l = (lane & 7) + (lane >> 4) * 8;
    int bk_l = ((lane >> 3) & 1) * 8;

    // per-lane smem byte offsets (without stage/ks)
    uint32_t a_off[4], b_off[4];
#pragma unroll
    for (int mi = 0; mi < 4; mi++)
        a_off[mi] = (uint32_t)(((wm * 64 + mi * 16 + ar) * SROW + ac) * 2);
#pragma unroll
    for (int nj2 = 0; nj2 < 4; nj2++)
        b_off[nj2] = (uint32_t)(((wn * 64 + nj2 * 16 + bn_l) * SROW + bk_l) * 2);

    float acc[4][8][4];
#pragma unroll
    for (int i = 0; i < 4; i++)
#pragma unroll
        for (int j = 0; j < 8; j++)
#pragma unroll
            for (int r = 0; r < 4; r++) acc[i][j][r] = 0.0f;

    // prologue: fill stage 0, one commit group
    {
        load_A_full(sb, 0, m0, tid);
#pragma unroll
        for (int sl = 0; sl < 4; sl++) load_B_slice(sb, 0, n0, tid, sl);
        cp_commit();
    }

    uint32_t a[2][4][4], b[2][4][4];

    // wait for stage 0, prime ks=0 frags
    cp_wait0();
    __syncthreads();
    uint32_t aS = sb, bS = sb + TILE_A_BYTES;
#pragma unroll
    for (int mi = 0; mi < 4; mi++) ldmx4(a[0][mi], aS + a_off[mi]);
#pragma unroll
    for (int nj2 = 0; nj2 < 4; nj2++) ldmx4(b[0][nj2], bS + b_off[nj2]);

    for (int kt = 0; kt < K_ITERS; kt++) {
        int nx = kt + 1;
        uint32_t nstg = sb + (nx & 1) * STAGE_BYTES;

#pragma unroll
        for (int ks = 0; ks < KS_STEPS; ks++) {
            int cur = ks & 1, nxt = cur ^ 1;

            // spread next-stage loads: A @ks0, B @ks1-4, commit @ks4
            if (nx < K_ITERS) {
                if (ks == 0)                 load_A_full(nstg, nx, m0, tid);
                else if (ks >= 1 && ks <= 4) load_B_slice(nstg, nx, n0, tid, ks - 1);
            }
            if (ks == 4) cp_commit();   // one group per tile (may be empty)

            if (ks < KS_STEPS - 1) {
                // prefetch next ks frags from current stage
                uint32_t ko = (uint32_t)((ks + 1) * 16 * 2);
#pragma unroll
                for (int mi = 0; mi < 4; mi++)
                    ldmx4(a[nxt][mi], aS + a_off[mi] + ko);
#pragma unroll
                for (int nj2 = 0; nj2 < 4; nj2++)
                    ldmx4(b[nxt][nj2], bS + b_off[nj2] + ko);
            } else if (nx < K_ITERS) {
                // next stage complete: wait, sync, prefetch its ks=0 frags
                cp_wait0();
                __syncthreads();
                aS = nstg;
                bS = nstg + TILE_A_BYTES;
#pragma unroll
                for (int mi = 0; mi < 4; mi++)
                    ldmx4(a[nxt][mi], aS + a_off[mi]);
#pragma unroll
                for (int nj2 = 0; nj2 < 4; nj2++)
                    ldmx4(b[nxt][nj2], bS + b_off[nj2]);
            }

#pragma unroll
            for (int mi = 0; mi < 4; mi++) {
#pragma unroll
                for (int nj = 0; nj < 8; nj++)
                    mma16816(acc[mi][nj], a[cur][mi], &b[cur][nj >> 1][(nj & 1) * 2]);
            }
        }
    }

    // epilogue: y = acc*scale + bias
    float scl = *scale_p;
    int gid = lane >> 2, tig = lane & 3;
#pragma unroll
    for (int mi = 0; mi < 4; mi++) {
        int row0 = m0 + wm * 64 + mi * 16 + gid;
#pragma unroll
        for (int nj = 0; nj < 8; nj++) {
            int col = n0 + wn * 64 + nj * 8 + 2 * tig;
            float2 bb = *(const float2*)&bias[col];
            float2 v0, v1;
            v0.x = fmaf(acc[mi][nj][0], scl, bb.x);
            v0.y = fmaf(acc[mi][nj][1], scl, bb.y);
            v1.x = fmaf(acc[mi][nj][2], scl, bb.x);
            v1.y = fmaf(acc[mi][nj][3], scl, bb.y);
            *(float2*)&out[(size_t)row0 * OUT_F + col] = v0;
            *(float2*)&out[(size_t)(row0 + 8) * OUT_F + col] = v1;
        }
    }
}

// ---------------------------------------------------------------------------
// Launch
// ---------------------------------------------------------------------------
extern "C" void kernel_launch(void* const* d_in, const int* in_sizes, int n_in,
                              void* d_out, int out_size) {
    const float* x     = (const float*)d_in[0];
    const int*   w     = (const int*)d_in[1];
    const float* scale = (const float*)d_in[2];
    const float* bias  = (const float*)d_in[3];
    float* out = (float*)d_out;

    cudaFuncSetAttribute(gemm_hmma_kernel,
                         cudaFuncAttributeMaxDynamicSharedMemorySize, SMEM_TOTAL);

    int nx4 = NROWS * IN_F / 4;
    int nw4 = OUT_F * IN_F / 4;
    k_convert_x<<<nx4 / 256, 256>>>((const float4*)x, nx4);
    k_convert_w<<<nw4 / 256, 256>>>((const int4*)w, nw4);

    gemm_hmma_kernel<<<TILES_M * TILES_N, THREADS, SMEM_TOTAL>>>(scale, bias, out);
}

// round 12
// speedup vs baseline: 1.0253x; 1.0253x over previous
#include <cuda_runtime.h>
#include <cuda_fp16.h>
#include <cstdint>

// ---------------------------------------------------------------------------
// QuantLinearTensorWise: y[8192,16384] = x[8192,4096] @ (W*scale)^T + bias
// Portable tensor-core path (compute_103 target): ldmatrix + mma.sync m16n8k16.
// R11: restore R8 mainloop (best: 2324us) — STAGES=4, BK=64, warp tile 64x64,
//      cross-tile frag pipeline, loads spread A@ks0/B@ks1/B@ks2.
//      Converts fused into ONE kernel (x + W partitioned by block).
// ---------------------------------------------------------------------------

#define IN_F   4096
#define OUT_F  16384
#define NROWS  8192

#define BM 128
#define BN 256
#define BK 64
#define STAGES 4
#define THREADS 256
#define K_ITERS (IN_F / BK)        // 64
#define TILES_M (NROWS / BM)       // 64
#define TILES_N (OUT_F / BN)       // 64
#define GROUP_M 8

// padded smem rows: 64 halves data + 8 halves pad = 72 halves = 144 bytes
#define SROW 72
#define TILE_A_BYTES (BM * SROW * 2)               // 18432
#define TILE_B_BYTES (BN * SROW * 2)               // 36864
#define STAGE_BYTES (TILE_A_BYTES + TILE_B_BYTES)  // 55296
#define SMEM_TOTAL (STAGES * STAGE_BYTES)          // 221184

// fp16 scratch
__device__ __half g_xh[(size_t)NROWS * IN_F];
__device__ __half g_wh[(size_t)OUT_F * IN_F];

// ---------------------------------------------------------------------------
// Fused conversion kernel: blocks [0, XB) convert x, [XB, XB+WB) convert W.
// x: 8M float4 chunks; W: 16M int4 chunks. 256 thr, 1 chunk/thr.
// ---------------------------------------------------------------------------
#define NX4 (NROWS * IN_F / 4)     // 8388608
#define NW4 (OUT_F * IN_F / 4)     // 16777216
#define XB  (NX4 / 256)            // 32768 blocks
#define WB  (NW4 / 256)            // 65536 blocks

__global__ void k_convert_fused(const float4* __restrict__ x,
                                const int4* __restrict__ w) {
    int b = blockIdx.x;
    if (b < XB) {
        int i = b * 256 + threadIdx.x;
        float4 v = x[i];
        __half2* o = reinterpret_cast<__half2*>(g_xh);
        o[2 * i]     = __floats2half2_rn(v.x, v.y);
        o[2 * i + 1] = __floats2half2_rn(v.z, v.w);
    } else {
        int i = (b - XB) * 256 + threadIdx.x;
        int4 v = w[i];
        __half2* o = reinterpret_cast<__half2*>(g_wh);
        o[2 * i]     = __halves2half2(__int2half_rn(v.x), __int2half_rn(v.y));
        o[2 * i + 1] = __halves2half2(__int2half_rn(v.z), __int2half_rn(v.w));
    }
}

// ---------------------------------------------------------------------------
// PTX helpers (portable sm_80+)
// ---------------------------------------------------------------------------
__device__ __forceinline__ uint32_t smem_u32(const void* p) {
    uint32_t a;
    asm("{ .reg .u64 t; cvta.to.shared.u64 t, %1; cvt.u32.u64 %0, t; }"
        : "=r"(a) : "l"(p));
    return a;
}

__device__ __forceinline__ void cp_async16(uint32_t dst, const void* src) {
    asm volatile("cp.async.cg.shared.global [%0], [%1], 16;"
                 :: "r"(dst), "l"(src) : "memory");
}

__device__ __forceinline__ void cp_commit() {
    asm volatile("cp.async.commit_group;" ::: "memory");
}

__device__ __forceinline__ void cp_wait2() {
    asm volatile("cp.async.wait_group 2;" ::: "memory");
}

__device__ __forceinline__ void ldmx4(uint32_t* r, uint32_t addr) {
    asm volatile("ldmatrix.sync.aligned.m8n8.x4.shared.b16 {%0,%1,%2,%3}, [%4];"
                 : "=r"(r[0]), "=r"(r[1]), "=r"(r[2]), "=r"(r[3]) : "r"(addr));
}

__device__ __forceinline__ void mma16816(float* d, const uint32_t* a,
                                         const uint32_t* b) {
    asm volatile(
        "mma.sync.aligned.m16n8k16.row.col.f32.f16.f16.f32 "
        "{%0,%1,%2,%3}, {%4,%5,%6,%7}, {%8,%9}, {%0,%1,%2,%3};"
        : "+f"(d[0]), "+f"(d[1]), "+f"(d[2]), "+f"(d[3])
        : "r"(a[0]), "r"(a[1]), "r"(a[2]), "r"(a[3]), "r"(b[0]), "r"(b[1]));
}

// ---------------------------------------------------------------------------
// Stage loads, split into three slices (A, B-half0, B-half1)
// ---------------------------------------------------------------------------
__device__ __forceinline__ void load_A(uint32_t stage_base, int kt,
                                       int m0, int tid) {
    int k0 = kt * BK;
#pragma unroll
    for (int h = 0; h < 4; h++) {
        int idx = tid + h * THREADS;
        int row = idx >> 3, c = idx & 7;
        uint32_t off = (uint32_t)(row * (SROW * 2) + c * 16);
        cp_async16(stage_base + off,
                   g_xh + (size_t)(m0 + row) * IN_F + k0 + c * 8);
    }
}

__device__ __forceinline__ void load_B(uint32_t stage_base, int kt,
                                       int n0, int tid, int half) {
    int k0 = kt * BK;
    uint32_t bB = stage_base + TILE_A_BYTES;
#pragma unroll
    for (int h = 0; h < 4; h++) {
        int idx = tid + (half * 4 + h) * THREADS;
        int row = idx >> 3, c = idx & 7;
        uint32_t off = (uint32_t)(row * (SROW * 2) + c * 16);
        cp_async16(bB + off, g_wh + (size_t)(n0 + row) * IN_F + k0 + c * 8);
    }
}

// ---------------------------------------------------------------------------
// GEMM kernel: warp grid 2(M) x 4(N), warp tile 64x64, cross-tile frag pipe
// ---------------------------------------------------------------------------
__global__ void __launch_bounds__(THREADS, 1)
gemm_hmma_kernel(const float* __restrict__ scale_p,
                 const float* __restrict__ bias,
                 float* __restrict__ out) {
    extern __shared__ char smem[];
    uint32_t sb = smem_u32(smem);
    int tid = threadIdx.x;
    int lane = tid & 31;
    int warp = tid >> 5;     // 0..7
    int wm = warp & 1;       // M dir: 64 rows
    int wn = warp >> 1;      // N dir: 0..3, 64 cols

    // tile raster with GROUP_M swizzle
    int pid = blockIdx.x;
    int per_group = GROUP_M * TILES_N;
    int g = pid / per_group;
    int rem = pid - g * per_group;
    int mt = g * GROUP_M + (rem % GROUP_M);
    int nt = rem / GROUP_M;
    int m0 = mt * BM, n0 = nt * BN;

    // ldmatrix lane address components (halves)
    int ar = (lane & 7) + ((lane >> 3) & 1) * 8;
    int ac = (lane >> 4) * 8;
    int bn_l = (lane & 7) + (lane >> 4) * 8;
    int bk_l = ((lane >> 3) & 1) * 8;

    // per-lane smem byte offsets (without stage/ks)
    uint32_t a_off[4], b_off[4];
#pragma unroll
    for (int mi = 0; mi < 4; mi++)
        a_off[mi] = (uint32_t)(((wm * 64 + mi * 16 + ar) * SROW + ac) * 2);
#pragma unroll
    for (int nj2 = 0; nj2 < 4; nj2++)
        b_off[nj2] = (uint32_t)(((wn * 64 + nj2 * 16 + bn_l) * SROW + bk_l) * 2);

    float acc[4][8][4];
#pragma unroll
    for (int i = 0; i < 4; i++)
#pragma unroll
        for (int j = 0; j < 8; j++)
#pragma unroll
            for (int r = 0; r < 4; r++) acc[i][j][r] = 0.0f;

    // prologue: fill STAGES-1 = 3 stages, one commit group each
#pragma unroll
    for (int s = 0; s < STAGES - 1; s++) {
        uint32_t st = sb + s * STAGE_BYTES;
        load_A(st, s, m0, tid);
        load_B(st, s, n0, tid, 0);
        load_B(st, s, n0, tid, 1);
        cp_commit();
    }

    uint32_t a[2][4][4], b[2][4][4];

    // wait for stage 0 (all but last 2 groups retired), prime ks=0 frags
    cp_wait2();
    __syncthreads();
    uint32_t aS = sb, bS = sb + TILE_A_BYTES;
#pragma unroll
    for (int mi = 0; mi < 4; mi++) ldmx4(a[0][mi], aS + a_off[mi]);
#pragma unroll
    for (int nj2 = 0; nj2 < 4; nj2++) ldmx4(b[0][nj2], bS + b_off[nj2]);

    for (int kt = 0; kt < K_ITERS; kt++) {
        int nx = kt + STAGES - 1;
        uint32_t nstg = sb + (nx % STAGES) * STAGE_BYTES;

#pragma unroll
        for (int ks = 0; ks < 4; ks++) {
            int cur = ks & 1, nxt = cur ^ 1;

            // spread gmem->smem issuance: A @ks0, B half @ks1, B half @ks2
            if (ks == 0) {
                if (nx < K_ITERS) load_A(nstg, nx, m0, tid);
            } else if (ks == 1) {
                if (nx < K_ITERS) load_B(nstg, nx, n0, tid, 0);
            } else if (ks == 2) {
                if (nx < K_ITERS) load_B(nstg, nx, n0, tid, 1);
                cp_commit();   // exactly one group per tile (may be empty)
            }

            if (ks < 3) {
                // prefetch next ks frags from current stage
                uint32_t ko = (uint32_t)((ks + 1) * 16 * 2);
#pragma unroll
                for (int mi = 0; mi < 4; mi++)
                    ldmx4(a[nxt][mi], aS + a_off[mi] + ko);
#pragma unroll
                for (int nj2 = 0; nj2 < 4; nj2++)
                    ldmx4(b[nxt][nj2], bS + b_off[nj2] + ko);
            } else if (kt + 1 < K_ITERS) {
                // next stage ready long ago (3-deep buffer): cheap wait
                cp_wait2();
                __syncthreads();
                uint32_t stg = sb + ((kt + 1) % STAGES) * STAGE_BYTES;
                aS = stg;
                bS = stg + TILE_A_BYTES;
#pragma unroll
                for (int mi = 0; mi < 4; mi++)
                    ldmx4(a[nxt][mi], aS + a_off[mi]);
#pragma unroll
                for (int nj2 = 0; nj2 < 4; nj2++)
                    ldmx4(b[nxt][nj2], bS + b_off[nj2]);
            }

#pragma unroll
            for (int mi = 0; mi < 4; mi++) {
#pragma unroll
                for (int nj = 0; nj < 8; nj++)
                    mma16816(acc[mi][nj], a[cur][mi], &b[cur][nj >> 1][(nj & 1) * 2]);
            }
        }
    }

    // epilogue: y = acc*scale + bias
    float scl = *scale_p;
    int gid = lane >> 2, tig = lane & 3;
#pragma unroll
    for (int mi = 0; mi < 4; mi++) {
        int row0 = m0 + wm * 64 + mi * 16 + gid;
#pragma unroll
        for (int nj = 0; nj < 8; nj++) {
            int col = n0 + wn * 64 + nj * 8 + 2 * tig;
            float2 bb = *(const float2*)&bias[col];
            float2 v0, v1;
            v0.x = fmaf(acc[mi][nj][0], scl, bb.x);
            v0.y = fmaf(acc[mi][nj][1], scl, bb.y);
            v1.x = fmaf(acc[mi][nj][2], scl, bb.x);
            v1.y = fmaf(acc[mi][nj][3], scl, bb.y);
            *(float2*)&out[(size_t)row0 * OUT_F + col] = v0;
            *(float2*)&out[(size_t)(row0 + 8) * OUT_F + col] = v1;
        }
    }
}

// ---------------------------------------------------------------------------
// Launch
// ---------------------------------------------------------------------------
extern "C" void kernel_launch(void* const* d_in, const int* in_sizes, int n_in,
                              void* d_out, int out_size) {
    const float* x     = (const float*)d_in[0];
    const int*   w     = (const int*)d_in[1];
    const float* scale = (const float*)d_in[2];
    const float* bias  = (const float*)d_in[3];
    float* out = (float*)d_out;

    cudaFuncSetAttribute(gemm_hmma_kernel,
                         cudaFuncAttributeMaxDynamicSharedMemorySize, SMEM_TOTAL);

    k_convert_fused<<<XB + WB, 256>>>((const float4*)x, (const int4*)w);
    gemm_hmma_kernel<<<TILES_M * TILES_N, THREADS, SMEM_TOTAL>>>(scale, bias, out);
}

// round 13
// speedup vs baseline: 1.0382x; 1.0126x over previous
#include <cuda_runtime.h>
#include <cuda_fp16.h>
#include <cstdint>

// ---------------------------------------------------------------------------
// QuantLinearTensorWise: y[8192,16384] = x[8192,4096] @ (W*scale)^T + bias
// Portable tensor-core path (compute_103 target): ldmatrix + mma.sync m16n8k16.
// R12: persistent CTAs (atomic work stealing) + cross-tile cp.async pipeline:
//      epilogue/prologue overlap with the next tile's loads. Mainloop = R8.
// ---------------------------------------------------------------------------

#define IN_F   4096
#define OUT_F  16384
#define NROWS  8192

#define BM 128
#define BN 256
#define BK 64
#define STAGES 4
#define THREADS 256
#define K_ITERS (IN_F / BK)        // 64  (multiple of STAGES -> stage = kt%4 global)
#define TILES_M (NROWS / BM)       // 64
#define TILES_N (OUT_F / BN)       // 64
#define NTILES (TILES_M * TILES_N) // 4096
#define GROUP_M 8
#define GRID 512

// padded smem rows: 64 halves data + 8 halves pad = 72 halves = 144 bytes
#define SROW 72
#define TILE_A_BYTES (BM * SROW * 2)               // 18432
#define TILE_B_BYTES (BN * SROW * 2)               // 36864
#define STAGE_BYTES (TILE_A_BYTES + TILE_B_BYTES)  // 55296
#define SMEM_STAGES (STAGES * STAGE_BYTES)         // 221184
#define SMEM_TOTAL (SMEM_STAGES + 16)              // + work-index slot

// fp16 scratch + work counter
__device__ __half g_xh[(size_t)NROWS * IN_F];
__device__ __half g_wh[(size_t)OUT_F * IN_F];
__device__ unsigned int g_tile_ctr;

// ---------------------------------------------------------------------------
// Fused conversion kernel (also resets the work counter for the GEMM)
// ---------------------------------------------------------------------------
#define NX4 (NROWS * IN_F / 4)     // 8388608
#define NW4 (OUT_F * IN_F / 4)     // 16777216
#define XB  (NX4 / 256)
#define WB  (NW4 / 256)

__global__ void k_convert_fused(const float4* __restrict__ x,
                                const int4* __restrict__ w) {
    int b = blockIdx.x;
    if (b == 0 && threadIdx.x == 0) g_tile_ctr = 0u;
    if (b < XB) {
        int i = b * 256 + threadIdx.x;
        float4 v = x[i];
        __half2* o = reinterpret_cast<__half2*>(g_xh);
        o[2 * i]     = __floats2half2_rn(v.x, v.y);
        o[2 * i + 1] = __floats2half2_rn(v.z, v.w);
    } else {
        int i = (b - XB) * 256 + threadIdx.x;
        int4 v = w[i];
        __half2* o = reinterpret_cast<__half2*>(g_wh);
        o[2 * i]     = __halves2half2(__int2half_rn(v.x), __int2half_rn(v.y));
        o[2 * i + 1] = __halves2half2(__int2half_rn(v.z), __int2half_rn(v.w));
    }
}

// ---------------------------------------------------------------------------
// PTX helpers (portable sm_80+)
// ---------------------------------------------------------------------------
__device__ __forceinline__ uint32_t smem_u32(const void* p) {
    uint32_t a;
    asm("{ .reg .u64 t; cvta.to.shared.u64 t, %1; cvt.u32.u64 %0, t; }"
        : "=r"(a) : "l"(p));
    return a;
}

__device__ __forceinline__ void cp_async16(uint32_t dst, const void* src) {
    asm volatile("cp.async.cg.shared.global [%0], [%1], 16;"
                 :: "r"(dst), "l"(src) : "memory");
}

__device__ __forceinline__ void cp_commit() {
    asm volatile("cp.async.commit_group;" ::: "memory");
}

__device__ __forceinline__ void cp_wait2() {
    asm volatile("cp.async.wait_group 2;" ::: "memory");
}

__device__ __forceinline__ void cp_wait_all() {
    asm volatile("cp.async.wait_group 0;" ::: "memory");
}

__device__ __forceinline__ void ldmx4(uint32_t* r, uint32_t addr) {
    asm volatile("ldmatrix.sync.aligned.m8n8.x4.shared.b16 {%0,%1,%2,%3}, [%4];"
                 : "=r"(r[0]), "=r"(r[1]), "=r"(r[2]), "=r"(r[3]) : "r"(addr));
}

__device__ __forceinline__ void mma16816(float* d, const uint32_t* a,
                                         const uint32_t* b) {
    asm volatile(
        "mma.sync.aligned.m16n8k16.row.col.f32.f16.f16.f32 "
        "{%0,%1,%2,%3}, {%4,%5,%6,%7}, {%8,%9}, {%0,%1,%2,%3};"
        : "+f"(d[0]), "+f"(d[1]), "+f"(d[2]), "+f"(d[3])
        : "r"(a[0]), "r"(a[1]), "r"(a[2]), "r"(a[3]), "r"(b[0]), "r"(b[1]));
}

// tile id -> (m0, n0) with GROUP_M raster swizzle
__device__ __forceinline__ void tile_coords(int t, int* m0, int* n0) {
    int per_group = GROUP_M * TILES_N;
    int g = t / per_group;
    int rem = t - g * per_group;
    int mt = g * GROUP_M + (rem % GROUP_M);
    int nt = rem / GROUP_M;
    *m0 = mt * BM;
    *n0 = nt * BN;
}

// ---------------------------------------------------------------------------
// Stage loads, split into three slices (A, B-half0, B-half1)
// ---------------------------------------------------------------------------
__device__ __forceinline__ void load_A(uint32_t stage_base, int kt,
                                       int m0, int tid) {
    int k0 = kt * BK;
#pragma unroll
    for (int h = 0; h < 4; h++) {
        int idx = tid + h * THREADS;
        int row = idx >> 3, c = idx & 7;
        uint32_t off = (uint32_t)(row * (SROW * 2) + c * 16);
        cp_async16(stage_base + off,
                   g_xh + (size_t)(m0 + row) * IN_F + k0 + c * 8);
    }
}

__device__ __forceinline__ void load_B(uint32_t stage_base, int kt,
                                       int n0, int tid, int half) {
    int k0 = kt * BK;
    uint32_t bB = stage_base + TILE_A_BYTES;
#pragma unroll
    for (int h = 0; h < 4; h++) {
        int idx = tid + (half * 4 + h) * THREADS;
        int row = idx >> 3, c = idx & 7;
        uint32_t off = (uint32_t)(row * (SROW * 2) + c * 16);
        cp_async16(bB + off, g_wh + (size_t)(n0 + row) * IN_F + k0 + c * 8);
    }
}

// ---------------------------------------------------------------------------
// Persistent GEMM kernel: warp grid 2(M) x 4(N), warp tile 64x64,
// cross-tile frag + stage pipeline
// ---------------------------------------------------------------------------
__global__ void __launch_bounds__(THREADS, 1)
gemm_hmma_kernel(const float* __restrict__ scale_p,
                 const float* __restrict__ bias,
                 float* __restrict__ out) {
    extern __shared__ char smem[];
    uint32_t sb = smem_u32(smem);
    volatile int* t_slot = (volatile int*)(smem + SMEM_STAGES);
    int tid = threadIdx.x;
    int lane = tid & 31;
    int warp = tid >> 5;     // 0..7
    int wm = warp & 1;       // M dir: 64 rows
    int wn = warp >> 1;      // N dir: 0..3, 64 cols

    // ldmatrix lane address components (halves)
    int ar = (lane & 7) + ((lane >> 3) & 1) * 8;
    int ac = (lane >> 4) * 8;
    int bn_l = (lane & 7) + (lane >> 4) * 8;
    int bk_l = ((lane >> 3) & 1) * 8;

    uint32_t a_off[4], b_off[4];
#pragma unroll
    for (int mi = 0; mi < 4; mi++)
        a_off[mi] = (uint32_t)(((wm * 64 + mi * 16 + ar) * SROW + ac) * 2);
#pragma unroll
    for (int nj2 = 0; nj2 < 4; nj2++)
        b_off[nj2] = (uint32_t)(((wn * 64 + nj2 * 16 + bn_l) * SROW + bk_l) * 2);

    // grab first tile
    if (tid == 0) t_slot[0] = (int)atomicAdd(&g_tile_ctr, 1u);
    __syncthreads();
    int t_cur = t_slot[0];
    if (t_cur >= NTILES) return;
    int m0, n0;
    tile_coords(t_cur, &m0, &n0);

    float acc[4][8][4];
#pragma unroll
    for (int i = 0; i < 4; i++)
#pragma unroll
        for (int j = 0; j < 8; j++)
#pragma unroll
            for (int r = 0; r < 4; r++) acc[i][j][r] = 0.0f;

    // prologue: fill stages 0..2 with (t_cur, kt=0..2)
#pragma unroll
    for (int s = 0; s < STAGES - 1; s++) {
        uint32_t st = sb + s * STAGE_BYTES;
        load_A(st, s, m0, tid);
        load_B(st, s, n0, tid, 0);
        load_B(st, s, n0, tid, 1);
        cp_commit();
    }

    // grab next tile (visible after the sync below)
    if (tid == 0) t_slot[0] = (int)atomicAdd(&g_tile_ctr, 1u);

    uint32_t a[2][4][4], b[2][4][4];

    cp_wait2();
    __syncthreads();
    int t_next = t_slot[0];
    int mn0 = 0, nn0 = 0;
    if (t_next < NTILES) tile_coords(t_next, &mn0, &nn0);

    uint32_t aS = sb, bS = sb + TILE_A_BYTES;
#pragma unroll
    for (int mi = 0; mi < 4; mi++) ldmx4(a[0][mi], aS + a_off[mi]);
#pragma unroll
    for (int nj2 = 0; nj2 < 4; nj2++) ldmx4(b[0][nj2], bS + b_off[nj2]);

    while (true) {
        for (int kt = 0; kt < K_ITERS; kt++) {
            int nx = kt + STAGES - 1;              // 3..66
            bool nx_in_cur = nx < K_ITERS;
            bool do_load = nx_in_cur || (t_next < NTILES);
            int lm0 = nx_in_cur ? m0 : mn0;
            int ln0 = nx_in_cur ? n0 : nn0;
            int lkt = nx_in_cur ? nx : nx - K_ITERS;
            uint32_t nstg = sb + (nx & 3) * STAGE_BYTES;

#pragma unroll
            for (int ks = 0; ks < 4; ks++) {
                int cur = ks & 1, nxt = cur ^ 1;

                if (ks == 0) {
                    if (do_load) load_A(nstg, lkt, lm0, tid);
                } else if (ks == 1) {
                    if (do_load) load_B(nstg, lkt, ln0, tid, 0);
                } else if (ks == 2) {
                    if (do_load) load_B(nstg, lkt, ln0, tid, 1);
                    cp_commit();   // one group per kt (may be empty)
                }

                if (ks < 3) {
                    uint32_t ko = (uint32_t)((ks + 1) * 16 * 2);
#pragma unroll
                    for (int mi = 0; mi < 4; mi++)
                        ldmx4(a[nxt][mi], aS + a_off[mi] + ko);
#pragma unroll
                    for (int nj2 = 0; nj2 < 4; nj2++)
                        ldmx4(b[nxt][nj2], bS + b_off[nj2] + ko);
                } else {
                    bool have_next = (kt + 1 < K_ITERS) || (t_next < NTILES);
                    if (have_next) {
                        cp_wait2();
                        __syncthreads();
                        uint32_t stg = sb + ((kt + 1) & 3) * STAGE_BYTES;
                        aS = stg;
                        bS = stg + TILE_A_BYTES;
#pragma unroll
                        for (int mi = 0; mi < 4; mi++)
                            ldmx4(a[nxt][mi], aS + a_off[mi]);
#pragma unroll
                        for (int nj2 = 0; nj2 < 4; nj2++)
                            ldmx4(b[nxt][nj2], bS + b_off[nj2]);
                    }
                }

#pragma unroll
                for (int mi = 0; mi < 4; mi++) {
#pragma unroll
                    for (int nj = 0; nj < 8; nj++)
                        mma16816(acc[mi][nj], a[cur][mi], &b[cur][nj >> 1][(nj & 1) * 2]);
                }
            }
        }

        // epilogue for t_cur (runs under the next tile's in-flight cp.asyncs)
        {
            float scl = *scale_p;
            int gid = lane >> 2, tig = lane & 3;
#pragma unroll
            for (int mi = 0; mi < 4; mi++) {
                int row0 = m0 + wm * 64 + mi * 16 + gid;
#pragma unroll
                for (int nj = 0; nj < 8; nj++) {
                    int col = n0 + wn * 64 + nj * 8 + 2 * tig;
                    float2 bb = *(const float2*)&bias[col];
                    float2 v0, v1;
                    v0.x = fmaf(acc[mi][nj][0], scl, bb.x);
                    v0.y = fmaf(acc[mi][nj][1], scl, bb.y);
                    v1.x = fmaf(acc[mi][nj][2], scl, bb.x);
                    v1.y = fmaf(acc[mi][nj][3], scl, bb.y);
                    *(float2*)&out[(size_t)row0 * OUT_F + col] = v0;
                    *(float2*)&out[(size_t)(row0 + 8) * OUT_F + col] = v1;
                    acc[mi][nj][0] = 0.0f;
                    acc[mi][nj][1] = 0.0f;
                    acc[mi][nj][2] = 0.0f;
                    acc[mi][nj][3] = 0.0f;
                }
            }
        }

        if (t_next >= NTILES) break;
        t_cur = t_next;
        m0 = mn0;
        n0 = nn0;
        if (tid == 0) t_slot[0] = (int)atomicAdd(&g_tile_ctr, 1u);
        __syncthreads();
        t_next = t_slot[0];
        if (t_next < NTILES) tile_coords(t_next, &mn0, &nn0);
        // frags for new tile's kt=0 were primed at the kt==63 ks==3 step;
        // stage rotation continues (64 % 4 == 0 keeps kt%4 globally consistent)
    }

    cp_wait_all();   // drain pending cp.asyncs before CTA exit
}

// ---------------------------------------------------------------------------
// Launch
// ---------------------------------------------------------------------------
extern "C" void kernel_launch(void* const* d_in, const int* in_sizes, int n_in,
                              void* d_out, int out_size) {
    const float* x     = (const float*)d_in[0];
    const int*   w     = (const int*)d_in[1];
    const float* scale = (const float*)d_in[2];
    const float* bias  = (const float*)d_in[3];
    float* out = (float*)d_out;

    cudaFuncSetAttribute(gemm_hmma_kernel,
                         cudaFuncAttributeMaxDynamicSharedMemorySize, SMEM_TOTAL);

    k_convert_fused<<<XB + WB, 256>>>((const float4*)x, (const int4*)w);
    gemm_hmma_kernel<<<GRID, THREADS, SMEM_TOTAL>>>(scale, bias, out);
}